// round 1
// baseline (speedup 1.0000x reference)
#include <cuda_runtime.h>
#include <cuda_bf16.h>
#include <cstdint>

// ---------------------------------------------------------------------------
// GraphNetBlock, GB300 round 1.
//   agg = segment_sum(edge_features, receivers)          (atomics)
//   new_nodes = LN( [node_f, agg] @ Wn + bn )            (fused affine MLP)
//   new_edges = LN( [nn[s], nn[r], edge_f] @ We + be )
// Wn = node_w1@node_w2 (256x128), bn = node_b1@node_w2 + node_b2. Same for edge.
// GEMMs: mma.sync.m16n8k16 bf16 with 3-term hi/lo split for fp32-level accuracy.
// ---------------------------------------------------------------------------

#define NMAX 50000

static __device__ float g_agg[(size_t)NMAX * 128];
static __device__ __nv_bfloat16 g_nwT_hi[128 * 256];
static __device__ __nv_bfloat16 g_nwT_lo[128 * 256];
static __device__ __nv_bfloat16 g_ewT_hi[128 * 384];
static __device__ __nv_bfloat16 g_ewT_lo[128 * 384];
static __device__ float g_nbias[128];
static __device__ float g_ebias[128];

// --------------------------- weight prep -----------------------------------
// 642 blocks x 128 threads. Block b computes one row k of the fused weight
// product W = W1 @ W2 (transposed store WT[n][k], split into bf16 hi/lo),
// or the fused bias b = b1 @ W2 + b2.
__global__ void prep_weights_kernel(
    const float* __restrict__ nw1, const float* __restrict__ nb1,
    const float* __restrict__ nw2, const float* __restrict__ nb2,
    const float* __restrict__ ew1, const float* __restrict__ eb1,
    const float* __restrict__ ew2, const float* __restrict__ eb2)
{
    const int b = blockIdx.x;
    const int n = threadIdx.x;  // output column 0..127
    const float* row; const float* w2;
    __nv_bfloat16* dh = nullptr; __nv_bfloat16* dl = nullptr;
    float* bd = nullptr;
    float extra = 0.0f;
    int pitch = 0, k = 0;
    if (b < 256) {
        row = nw1 + (size_t)b * 128; w2 = nw2;
        dh = g_nwT_hi; dl = g_nwT_lo; pitch = 256; k = b;
    } else if (b == 256) {
        row = nb1; w2 = nw2; bd = g_nbias; extra = nb2[n];
    } else if (b < 641) {
        k = b - 257;
        row = ew1 + (size_t)k * 128; w2 = ew2;
        dh = g_ewT_hi; dl = g_ewT_lo; pitch = 384;
    } else {
        row = eb1; w2 = ew2; bd = g_ebias; extra = eb2[n];
    }
    float s = extra;
    #pragma unroll 4
    for (int j = 0; j < 128; j++)
        s = fmaf(row[j], w2[j * 128 + n], s);
    if (bd) {
        bd[n] = s;
    } else {
        __nv_bfloat16 h = __float2bfloat16(s);
        float r = s - __bfloat162float(h);
        dh[(size_t)n * pitch + k] = h;
        dl[(size_t)n * pitch + k] = __float2bfloat16(r);
    }
}

// --------------------------- agg zero + scatter ----------------------------
__global__ void zero_agg_kernel(int n4)
{
    int i = blockIdx.x * blockDim.x + threadIdx.x;
    if (i < n4)
        reinterpret_cast<float4*>(g_agg)[i] = make_float4(0.f, 0.f, 0.f, 0.f);
}

// One warp per edge; lane c handles float4 chunk c of the 128-wide row.
__global__ void scatter_add_kernel(const float* __restrict__ ef,
                                   const int* __restrict__ recv, int E)
{
    long long t = (long long)blockIdx.x * blockDim.x + threadIdx.x;
    int e = (int)(t >> 5);
    if (e >= E) return;
    int c = (int)(t & 31);
    float4 v = reinterpret_cast<const float4*>(ef)[(size_t)e * 32 + c];
    float* dst = g_agg + (size_t)recv[e] * 128 + c * 4;
    atomicAdd(dst + 0, v.x);
    atomicAdd(dst + 1, v.y);
    atomicAdd(dst + 2, v.z);
    atomicAdd(dst + 3, v.w);
}

// --------------------------- fused GEMM + bias + LN ------------------------
__device__ __forceinline__ void mma16816(float c[4], const uint32_t a[4],
                                         uint32_t b0, uint32_t b1)
{
    asm volatile(
        "mma.sync.aligned.m16n8k16.row.col.f32.bf16.bf16.f32 "
        "{%0,%1,%2,%3}, {%4,%5,%6,%7}, {%8,%9}, {%0,%1,%2,%3};"
        : "+f"(c[0]), "+f"(c[1]), "+f"(c[2]), "+f"(c[3])
        : "r"(a[0]), "r"(a[1]), "r"(a[2]), "r"(a[3]), "r"(b0), "r"(b1));
}

__device__ __forceinline__ void split_f2(float2 v, uint32_t& hi, uint32_t& lo)
{
    __nv_bfloat162 h = __float22bfloat162_rn(v);
    float2 hf = __bfloat1622float2(h);
    float2 r;
    r.x = v.x - hf.x;
    r.y = v.y - hf.y;
    __nv_bfloat162 l = __float22bfloat162_rn(r);
    hi = *reinterpret_cast<uint32_t*>(&h);
    lo = *reinterpret_cast<uint32_t*>(&l);
}

// MODE 0: node pass (segments: node_features, g_agg), K = 256 (NCHUNK=4)
// MODE 1: edge pass (segments: nn[senders], nn[receivers], edge_f), K = 384 (NCHUNK=6)
// CTA = 256 threads (8 warps), tile = 128 rows x 128 cols. Warp w owns rows
// w*16..w*16+15. B (weight) chunk of 64 K-columns staged in SMEM (pitch 72 bf16
// -> conflict-free). A fragments loaded straight from gmem (gather-friendly).
template<int MODE, int NCHUNK>
__global__ __launch_bounds__(256) void mlp_ln_kernel(
    const float* __restrict__ xA,   // node_features (MODE 0) / new_nodes (MODE 1)
    const float* __restrict__ xB,   // unused (MODE 0)        / edge_features (MODE 1)
    const int* __restrict__ senders,
    const int* __restrict__ receivers,
    const float* __restrict__ ln_g,
    const float* __restrict__ ln_b,
    float* __restrict__ out, int M)
{
    constexpr int K = NCHUNK * 64;
    __shared__ __nv_bfloat16 SBh[128 * 72];
    __shared__ __nv_bfloat16 SBl[128 * 72];
    __shared__ float s_bias[128], s_g[128], s_b[128];

    const int tid = threadIdx.x;
    const int warp = tid >> 5, lane = tid & 31;
    const int g = lane >> 2, q = lane & 3;

    if (tid < 128) {
        s_bias[tid] = MODE ? g_ebias[tid] : g_nbias[tid];
        s_g[tid] = ln_g[tid];
        s_b[tid] = ln_b[tid];
    }

    const int row0 = blockIdx.x * 128 + warp * 16 + g;
    const int row1 = row0 + 8;
    const int r0c = min(row0, M - 1);
    const int r1c = min(row1, M - 1);

    const float* pA[3];
    const float* pB[3];
    if (MODE == 0) {
        pA[0] = xA + (size_t)r0c * 128;
        pB[0] = xA + (size_t)r1c * 128;
        pA[1] = g_agg + (size_t)r0c * 128;
        pB[1] = g_agg + (size_t)r1c * 128;
        pA[2] = pA[0];  // unused
        pB[2] = pB[0];
    } else {
        int s0 = senders[r0c], s1 = senders[r1c];
        int d0 = receivers[r0c], d1 = receivers[r1c];
        pA[0] = xA + (size_t)s0 * 128;
        pB[0] = xA + (size_t)s1 * 128;
        pA[1] = xA + (size_t)d0 * 128;
        pB[1] = xA + (size_t)d1 * 128;
        pA[2] = xB + (size_t)r0c * 128;
        pB[2] = xB + (size_t)r1c * 128;
    }
    const __nv_bfloat16* __restrict__ Whi = MODE ? g_ewT_hi : g_nwT_hi;
    const __nv_bfloat16* __restrict__ Wlo = MODE ? g_ewT_lo : g_nwT_lo;

    float acc[16][4];
    #pragma unroll
    for (int i = 0; i < 16; i++) {
        acc[i][0] = 0.f; acc[i][1] = 0.f; acc[i][2] = 0.f; acc[i][3] = 0.f;
    }

    #pragma unroll
    for (int kc = 0; kc < NCHUNK; kc++) {
        __syncthreads();
        // Cooperative load of 128x64 bf16 weight chunk (hi+lo) into padded SMEM.
        #pragma unroll
        for (int i = 0; i < 4; i++) {
            int idx = tid + i * 256;         // 0..1023
            int n = idx >> 3, j = idx & 7;   // row, int4-within-row
            reinterpret_cast<int4*>(SBh + n * 72)[j] =
                reinterpret_cast<const int4*>(Whi + (size_t)n * K + kc * 64)[j];
            reinterpret_cast<int4*>(SBl + n * 72)[j] =
                reinterpret_cast<const int4*>(Wlo + (size_t)n * K + kc * 64)[j];
        }
        __syncthreads();

        const int seg = kc >> 1;             // compile-time after unroll
        const float* pa = pA[seg];
        const float* pb = pB[seg];
        const int cbase = (kc & 1) * 64;

        #pragma unroll 1
        for (int ks = 0; ks < 4; ks++) {
            const int c0 = ks * 16 + q * 2;
            float2 x00 = *reinterpret_cast<const float2*>(pa + cbase + c0);
            float2 x10 = *reinterpret_cast<const float2*>(pb + cbase + c0);
            float2 x01 = *reinterpret_cast<const float2*>(pa + cbase + c0 + 8);
            float2 x11 = *reinterpret_cast<const float2*>(pb + cbase + c0 + 8);
            uint32_t ah[4], al[4];
            split_f2(x00, ah[0], al[0]);
            split_f2(x10, ah[1], al[1]);
            split_f2(x01, ah[2], al[2]);
            split_f2(x11, ah[3], al[3]);
            #pragma unroll
            for (int nt = 0; nt < 16; nt++) {
                const int n = nt * 8 + g;
                const __nv_bfloat16* rh = SBh + n * 72 + c0;
                const __nv_bfloat16* rl = SBl + n * 72 + c0;
                uint32_t bh0 = *reinterpret_cast<const uint32_t*>(rh);
                uint32_t bh1 = *reinterpret_cast<const uint32_t*>(rh + 8);
                uint32_t bl0 = *reinterpret_cast<const uint32_t*>(rl);
                uint32_t bl1 = *reinterpret_cast<const uint32_t*>(rl + 8);
                mma16816(acc[nt], ah, bh0, bh1);
                mma16816(acc[nt], al, bh0, bh1);
                mma16816(acc[nt], ah, bl0, bl1);
            }
        }
    }

    // ---------------- epilogue: bias + layernorm + store -------------------
    float sum0 = 0.f, sq0 = 0.f, sum1 = 0.f, sq1 = 0.f;
    #pragma unroll
    for (int nt = 0; nt < 16; nt++) {
        const int c = nt * 8 + q * 2;
        const float b0 = s_bias[c], b1 = s_bias[c + 1];
        float v0 = acc[nt][0] + b0, v1 = acc[nt][1] + b1;
        float v2 = acc[nt][2] + b0, v3 = acc[nt][3] + b1;
        acc[nt][0] = v0; acc[nt][1] = v1; acc[nt][2] = v2; acc[nt][3] = v3;
        sum0 += v0 + v1; sq0 += v0 * v0 + v1 * v1;
        sum1 += v2 + v3; sq1 += v2 * v2 + v3 * v3;
    }
    #pragma unroll
    for (int m = 1; m <= 2; m <<= 1) {
        sum0 += __shfl_xor_sync(0xffffffffu, sum0, m);
        sq0  += __shfl_xor_sync(0xffffffffu, sq0, m);
        sum1 += __shfl_xor_sync(0xffffffffu, sum1, m);
        sq1  += __shfl_xor_sync(0xffffffffu, sq1, m);
    }
    const float inv = 1.0f / 128.0f;
    const float mu0 = sum0 * inv, mu1 = sum1 * inv;
    const float rs0 = rsqrtf(fmaxf(sq0 * inv - mu0 * mu0, 0.f) + 1e-5f);
    const float rs1 = rsqrtf(fmaxf(sq1 * inv - mu1 * mu1, 0.f) + 1e-5f);

    if (row0 < M) {
        float* o = out + (size_t)row0 * 128;
        #pragma unroll
        for (int nt = 0; nt < 16; nt++) {
            const int c = nt * 8 + q * 2;
            float2 w;
            w.x = (acc[nt][0] - mu0) * rs0 * s_g[c] + s_b[c];
            w.y = (acc[nt][1] - mu0) * rs0 * s_g[c + 1] + s_b[c + 1];
            *reinterpret_cast<float2*>(o + c) = w;
        }
    }
    if (row1 < M) {
        float* o = out + (size_t)row1 * 128;
        #pragma unroll
        for (int nt = 0; nt < 16; nt++) {
            const int c = nt * 8 + q * 2;
            float2 w;
            w.x = (acc[nt][2] - mu1) * rs1 * s_g[c] + s_b[c];
            w.y = (acc[nt][3] - mu1) * rs1 * s_g[c + 1] + s_b[c + 1];
            *reinterpret_cast<float2*>(o + c) = w;
        }
    }
}

// ---------------------------------------------------------------------------
extern "C" void kernel_launch(void* const* d_in, const int* in_sizes, int n_in,
                              void* d_out, int out_size)
{
    const float* node_f   = (const float*)d_in[0];
    const float* edge_f   = (const float*)d_in[1];
    const int*   senders  = (const int*)d_in[2];
    const int*   receivers= (const int*)d_in[3];
    const float* nw1 = (const float*)d_in[4];
    const float* nb1 = (const float*)d_in[5];
    const float* nw2 = (const float*)d_in[6];
    const float* nb2 = (const float*)d_in[7];
    const float* nlg = (const float*)d_in[8];
    const float* nlb = (const float*)d_in[9];
    const float* ew1 = (const float*)d_in[10];
    const float* eb1 = (const float*)d_in[11];
    const float* ew2 = (const float*)d_in[12];
    const float* eb2 = (const float*)d_in[13];
    const float* elg = (const float*)d_in[14];
    const float* elb = (const float*)d_in[15];

    const int N = in_sizes[0] / 128;   // 50000
    const int E = in_sizes[2];         // 300000

    float* out_nodes = (float*)d_out;
    float* out_edges = out_nodes + (size_t)N * 128;

    // 1) fuse W1@W2 (+ bias) once, transpose, split to bf16 hi/lo
    prep_weights_kernel<<<642, 128>>>(nw1, nb1, nw2, nb2, ew1, eb1, ew2, eb2);

    // 2) agg = segment_sum(edge_features, receivers)
    zero_agg_kernel<<<(N * 32 + 255) / 256, 256>>>(N * 32);
    {
        long long threads = (long long)E * 32;
        int grid = (int)((threads + 255) / 256);
        scatter_add_kernel<<<grid, 256>>>(edge_f, receivers, E);
    }

    // 3) node pass: LN([node_f, agg] @ Wn + bn) -> out_nodes
    mlp_ln_kernel<0, 4><<<(N + 127) / 128, 256>>>(
        node_f, nullptr, nullptr, nullptr, nlg, nlb, out_nodes, N);

    // 4) edge pass: LN([nn[s], nn[r], edge_f] @ We + be) -> out_edges
    mlp_ln_kernel<1, 6><<<(E + 127) / 128, 256>>>(
        out_nodes, edge_f, senders, receivers, elg, elb, out_edges, E);
}

// round 3
// speedup vs baseline: 1.2314x; 1.2314x over previous
#include <cuda_runtime.h>
#include <cuda_bf16.h>
#include <cstdint>

// ---------------------------------------------------------------------------
// GraphNetBlock, GB300 round 2.
//   agg = segment_sum(edge_features, receivers)             (red.v4 atomics)
//   new_nodes = LN( [node_f, agg] @ Wn + bn )
//   P         = new_nodes @ [We_s | We_r]        (50k x 256, per-NODE)
//   new_edges = LN( ef @ We_e + P[s,0:128] + P[r,128:256] + be )
// Wn = node_w1@node_w2 etc (affine MLP collapses; no activation in ref).
// GEMMs: mma.sync m16n8k16 bf16, 3-term hi/lo split, ldmatrix B fragments.
// ---------------------------------------------------------------------------

#define NMAX 50000

static __device__ float g_agg[(size_t)NMAX * 128];
static __device__ float g_P[(size_t)NMAX * 256];
static __device__ __nv_bfloat16 g_nwT_hi[128 * 256];   // node fused W^T, pitch 256
static __device__ __nv_bfloat16 g_nwT_lo[128 * 256];
static __device__ __nv_bfloat16 g_PwT_hi[256 * 128];   // [We_s|We_r]^T, pitch 128
static __device__ __nv_bfloat16 g_PwT_lo[256 * 128];
static __device__ __nv_bfloat16 g_CwT_hi[128 * 128];   // We_e^T, pitch 128
static __device__ __nv_bfloat16 g_CwT_lo[128 * 128];
static __device__ float g_nbias[128];
static __device__ float g_ebias[128];

// --------------------------- weight prep -----------------------------------
// 642 blocks x 128 threads. Block b computes one row k of W1@W2 (stored
// transposed, split bf16 hi/lo) or a fused bias.
__global__ void prep_weights_kernel(
    const float* __restrict__ nw1, const float* __restrict__ nb1,
    const float* __restrict__ nw2, const float* __restrict__ nb2,
    const float* __restrict__ ew1, const float* __restrict__ eb1,
    const float* __restrict__ ew2, const float* __restrict__ eb2)
{
    const int b = blockIdx.x;
    const int n = threadIdx.x;  // output column 0..127
    const float* row; const float* w2;
    __nv_bfloat16* dh = nullptr; __nv_bfloat16* dl = nullptr;
    float* bd = nullptr;
    float extra = 0.0f;
    int pitch = 0, kk = 0, row_off = 0;
    if (b < 256) {
        row = nw1 + (size_t)b * 128; w2 = nw2;
        dh = g_nwT_hi; dl = g_nwT_lo; pitch = 256; kk = b;
    } else if (b == 256) {
        row = nb1; w2 = nw2; bd = g_nbias; extra = nb2[n];
    } else if (b < 641) {
        int k = b - 257;           // 0..383 into edge W
        row = ew1 + (size_t)k * 128; w2 = ew2;
        if (k < 128)      { dh = g_PwT_hi; dl = g_PwT_lo; pitch = 128; row_off = 0;   kk = k; }
        else if (k < 256) { dh = g_PwT_hi; dl = g_PwT_lo; pitch = 128; row_off = 128; kk = k - 128; }
        else              { dh = g_CwT_hi; dl = g_CwT_lo; pitch = 128; row_off = 0;   kk = k - 256; }
    } else {
        row = eb1; w2 = ew2; bd = g_ebias; extra = eb2[n];
    }
    float s = extra;
    #pragma unroll 4
    for (int j = 0; j < 128; j++)
        s = fmaf(row[j], w2[j * 128 + n], s);
    if (bd) {
        bd[n] = s;
    } else {
        __nv_bfloat16 h = __float2bfloat16(s);
        float r = s - __bfloat162float(h);
        dh[(size_t)(row_off + n) * pitch + kk] = h;
        dl[(size_t)(row_off + n) * pitch + kk] = __float2bfloat16(r);
    }
}

// --------------------------- agg zero + scatter ----------------------------
__global__ void zero_agg_kernel(int n4)
{
    int i = blockIdx.x * blockDim.x + threadIdx.x;
    if (i < n4)
        reinterpret_cast<float4*>(g_agg)[i] = make_float4(0.f, 0.f, 0.f, 0.f);
}

// One warp per edge; lane c handles float4 chunk c (vector reduction to L2).
__global__ void scatter_add_kernel(const float* __restrict__ ef,
                                   const int* __restrict__ recv, int E)
{
    long long t = (long long)blockIdx.x * blockDim.x + threadIdx.x;
    int e = (int)(t >> 5);
    if (e >= E) return;
    int c = (int)(t & 31);
    float4 v = reinterpret_cast<const float4*>(ef)[(size_t)e * 32 + c];
    float* dst = g_agg + (size_t)recv[e] * 128 + c * 4;
    asm volatile("red.global.add.v4.f32 [%0], {%1,%2,%3,%4};"
                 :: "l"(dst), "f"(v.x), "f"(v.y), "f"(v.z), "f"(v.w)
                 : "memory");
}

// --------------------------- mma helpers -----------------------------------
__device__ __forceinline__ void mma16816(float c[4], const uint32_t a[4],
                                         uint32_t b0, uint32_t b1)
{
    asm volatile(
        "mma.sync.aligned.m16n8k16.row.col.f32.bf16.bf16.f32 "
        "{%0,%1,%2,%3}, {%4,%5,%6,%7}, {%8,%9}, {%0,%1,%2,%3};"
        : "+f"(c[0]), "+f"(c[1]), "+f"(c[2]), "+f"(c[3])
        : "r"(a[0]), "r"(a[1]), "r"(a[2]), "r"(a[3]), "r"(b0), "r"(b1));
}

__device__ __forceinline__ void ldsm4(uint32_t& r0, uint32_t& r1,
                                      uint32_t& r2, uint32_t& r3,
                                      const __nv_bfloat16* p)
{
    uint32_t a = (uint32_t)__cvta_generic_to_shared(p);
    asm volatile("ldmatrix.sync.aligned.m8n8.x4.shared.b16 {%0,%1,%2,%3}, [%4];"
                 : "=r"(r0), "=r"(r1), "=r"(r2), "=r"(r3) : "r"(a));
}

__device__ __forceinline__ void split_f2(float2 v, uint32_t& hi, uint32_t& lo)
{
    __nv_bfloat162 h = __float22bfloat162_rn(v);
    float2 hf = __bfloat1622float2(h);
    float2 r;
    r.x = v.x - hf.x;
    r.y = v.y - hf.y;
    __nv_bfloat162 l = __float22bfloat162_rn(r);
    hi = *reinterpret_cast<uint32_t*>(&h);
    lo = *reinterpret_cast<uint32_t*>(&l);
}

// --------------------------- fused GEMM kernels ----------------------------
// MODE 0: node pass.  A = [node_f | g_agg], K=256, epi: +nbias, LN -> out.
// MODE 1: P pass.     A = new_nodes (xA), K=128, W col-block = blockIdx.y,
//                     epi: plain store into g_P (pitch 256).
// MODE 2: edge pass.  A = edge_f (xA), K=128,
//                     epi: + g_P[s,0:128] + g_P[r,128:256] + ebias, LN -> out.
// CTA = 256 threads (8 warps), tile 128 rows x 128 cols; warp w rows w*16..+15.
template<int MODE, int NCHUNK>
__global__ __launch_bounds__(256) void mlp_ln_kernel(
    const float* __restrict__ xA,
    const int* __restrict__ senders,
    const int* __restrict__ receivers,
    const float* __restrict__ ln_g,
    const float* __restrict__ ln_b,
    float* __restrict__ out, int M)
{
    __shared__ __nv_bfloat16 SBh[128 * 72];
    __shared__ __nv_bfloat16 SBl[128 * 72];
    __shared__ float s_bias[128], s_g[128], s_b[128];

    const int tid = threadIdx.x;
    const int warp = tid >> 5, lane = tid & 31;
    const int g = lane >> 2, q = lane & 3;
    const int laneRow = ((lane >> 4) << 3) + (lane & 7);
    const int laneK = ((lane >> 3) & 1) << 3;

    if (MODE != 1 && tid < 128) {
        s_bias[tid] = MODE ? g_ebias[tid] : g_nbias[tid];
        s_g[tid] = ln_g[tid];
        s_b[tid] = ln_b[tid];
    }

    const int row0 = blockIdx.x * 128 + warp * 16 + g;
    const int row1 = row0 + 8;
    const int r0c = min(row0, M - 1);
    const int r1c = min(row1, M - 1);

    const float* pA0 = xA + (size_t)r0c * 128;
    const float* pA1 = xA + (size_t)r1c * 128;
    const float* pG0 = g_agg + (size_t)r0c * 128;   // MODE 0 only
    const float* pG1 = g_agg + (size_t)r1c * 128;

    const __nv_bfloat16* Whi;
    const __nv_bfloat16* Wlo;
    int wpitch;
    int ncol0 = 0;
    if (MODE == 0) { Whi = g_nwT_hi; Wlo = g_nwT_lo; wpitch = 256; }
    else if (MODE == 1) {
        ncol0 = blockIdx.y * 128;
        Whi = g_PwT_hi + (size_t)ncol0 * 128;
        Wlo = g_PwT_lo + (size_t)ncol0 * 128;
        wpitch = 128;
    } else { Whi = g_CwT_hi; Wlo = g_CwT_lo; wpitch = 128; }

    float acc[16][4];
    #pragma unroll
    for (int i = 0; i < 16; i++) {
        acc[i][0] = 0.f; acc[i][1] = 0.f; acc[i][2] = 0.f; acc[i][3] = 0.f;
    }

    #pragma unroll
    for (int kc = 0; kc < NCHUNK; kc++) {
        __syncthreads();
        #pragma unroll
        for (int i = 0; i < 4; i++) {
            int idx = tid + i * 256;         // 0..1023
            int n = idx >> 3, j = idx & 7;   // smem row, int4-within-row
            reinterpret_cast<int4*>(SBh + n * 72)[j] =
                reinterpret_cast<const int4*>(Whi + (size_t)n * wpitch + kc * 64)[j];
            reinterpret_cast<int4*>(SBl + n * 72)[j] =
                reinterpret_cast<const int4*>(Wlo + (size_t)n * wpitch + kc * 64)[j];
        }
        __syncthreads();

        const float* pa;
        const float* pb;
        int cbase;
        if (MODE == 0) {
            pa = (kc < 2) ? pA0 : pG0;
            pb = (kc < 2) ? pA1 : pG1;
            cbase = (kc & 1) * 64;
        } else {
            pa = pA0; pb = pA1; cbase = kc * 64;
        }

        #pragma unroll 1
        for (int ks = 0; ks < 4; ks++) {
            const int c0 = ks * 16 + q * 2;
            float2 x00 = *reinterpret_cast<const float2*>(pa + cbase + c0);
            float2 x10 = *reinterpret_cast<const float2*>(pb + cbase + c0);
            float2 x01 = *reinterpret_cast<const float2*>(pa + cbase + c0 + 8);
            float2 x11 = *reinterpret_cast<const float2*>(pb + cbase + c0 + 8);
            uint32_t ah[4], al[4];
            split_f2(x00, ah[0], al[0]);
            split_f2(x10, ah[1], al[1]);
            split_f2(x01, ah[2], al[2]);
            split_f2(x11, ah[3], al[3]);

            const int kcol = ks * 16 + laneK;
            #pragma unroll
            for (int nt2 = 0; nt2 < 8; nt2++) {
                const int srow = nt2 * 16 + laneRow;
                uint32_t h0, h1, h2, h3, l0, l1, l2, l3;
                ldsm4(h0, h1, h2, h3, SBh + srow * 72 + kcol);
                ldsm4(l0, l1, l2, l3, SBl + srow * 72 + kcol);
                mma16816(acc[2 * nt2],     ah, h0, h1);
                mma16816(acc[2 * nt2 + 1], ah, h2, h3);
                mma16816(acc[2 * nt2],     al, h0, h1);
                mma16816(acc[2 * nt2 + 1], al, h2, h3);
                mma16816(acc[2 * nt2],     ah, l0, l1);
                mma16816(acc[2 * nt2 + 1], ah, l2, l3);
            }
        }
    }

    // ---------------- epilogues -------------------------------------------
    if (MODE == 1) {
        // plain store into g_P (pitch 256)
        if (row0 < M) {
            float* o = g_P + (size_t)row0 * 256 + ncol0;
            #pragma unroll
            for (int nt = 0; nt < 16; nt++) {
                const int c = nt * 8 + q * 2;
                *reinterpret_cast<float2*>(o + c) = make_float2(acc[nt][0], acc[nt][1]);
            }
        }
        if (row1 < M) {
            float* o = g_P + (size_t)row1 * 256 + ncol0;
            #pragma unroll
            for (int nt = 0; nt < 16; nt++) {
                const int c = nt * 8 + q * 2;
                *reinterpret_cast<float2*>(o + c) = make_float2(acc[nt][2], acc[nt][3]);
            }
        }
        return;
    }

    if (MODE == 2) {
        // add gathered P contributions: P[s,0:128] + P[r,128:256]
        const int s0 = senders[r0c], s1 = senders[r1c];
        const int d0 = receivers[r0c], d1 = receivers[r1c];
        const float* Ps0 = g_P + (size_t)s0 * 256;
        const float* Ps1 = g_P + (size_t)s1 * 256;
        const float* Pd0 = g_P + (size_t)d0 * 256 + 128;
        const float* Pd1 = g_P + (size_t)d1 * 256 + 128;
        #pragma unroll
        for (int nt = 0; nt < 16; nt++) {
            const int c = nt * 8 + q * 2;
            float2 a0 = *reinterpret_cast<const float2*>(Ps0 + c);
            float2 b0 = *reinterpret_cast<const float2*>(Pd0 + c);
            float2 a1 = *reinterpret_cast<const float2*>(Ps1 + c);
            float2 b1 = *reinterpret_cast<const float2*>(Pd1 + c);
            acc[nt][0] += a0.x + b0.x;
            acc[nt][1] += a0.y + b0.y;
            acc[nt][2] += a1.x + b1.x;
            acc[nt][3] += a1.y + b1.y;
        }
    }

    // bias + layernorm + store (MODE 0 and 2)
    float sum0 = 0.f, sq0 = 0.f, sum1 = 0.f, sq1 = 0.f;
    #pragma unroll
    for (int nt = 0; nt < 16; nt++) {
        const int c = nt * 8 + q * 2;
        const float b0 = s_bias[c], b1 = s_bias[c + 1];
        float v0 = acc[nt][0] + b0, v1 = acc[nt][1] + b1;
        float v2 = acc[nt][2] + b0, v3 = acc[nt][3] + b1;
        acc[nt][0] = v0; acc[nt][1] = v1; acc[nt][2] = v2; acc[nt][3] = v3;
        sum0 += v0 + v1; sq0 += v0 * v0 + v1 * v1;
        sum1 += v2 + v3; sq1 += v2 * v2 + v3 * v3;
    }
    #pragma unroll
    for (int m = 1; m <= 2; m <<= 1) {
        sum0 += __shfl_xor_sync(0xffffffffu, sum0, m);
        sq0  += __shfl_xor_sync(0xffffffffu, sq0, m);
        sum1 += __shfl_xor_sync(0xffffffffu, sum1, m);
        sq1  += __shfl_xor_sync(0xffffffffu, sq1, m);
    }
    const float inv = 1.0f / 128.0f;
    const float mu0 = sum0 * inv, mu1 = sum1 * inv;
    const float rs0 = rsqrtf(fmaxf(sq0 * inv - mu0 * mu0, 0.f) + 1e-5f);
    const float rs1 = rsqrtf(fmaxf(sq1 * inv - mu1 * mu1, 0.f) + 1e-5f);

    if (row0 < M) {
        float* o = out + (size_t)row0 * 128;
        #pragma unroll
        for (int nt = 0; nt < 16; nt++) {
            const int c = nt * 8 + q * 2;
            float2 w;
            w.x = (acc[nt][0] - mu0) * rs0 * s_g[c] + s_b[c];
            w.y = (acc[nt][1] - mu0) * rs0 * s_g[c + 1] + s_b[c + 1];
            *reinterpret_cast<float2*>(o + c) = w;
        }
    }
    if (row1 < M) {
        float* o = out + (size_t)row1 * 128;
        #pragma unroll
        for (int nt = 0; nt < 16; nt++) {
            const int c = nt * 8 + q * 2;
            float2 w;
            w.x = (acc[nt][2] - mu1) * rs1 * s_g[c] + s_b[c];
            w.y = (acc[nt][3] - mu1) * rs1 * s_g[c + 1] + s_b[c + 1];
            *reinterpret_cast<float2*>(o + c) = w;
        }
    }
}

// ---------------------------------------------------------------------------
extern "C" void kernel_launch(void* const* d_in, const int* in_sizes, int n_in,
                              void* d_out, int out_size)
{
    const float* node_f   = (const float*)d_in[0];
    const float* edge_f   = (const float*)d_in[1];
    const int*   senders  = (const int*)d_in[2];
    const int*   receivers= (const int*)d_in[3];
    const float* nw1 = (const float*)d_in[4];
    const float* nb1 = (const float*)d_in[5];
    const float* nw2 = (const float*)d_in[6];
    const float* nb2 = (const float*)d_in[7];
    const float* nlg = (const float*)d_in[8];
    const float* nlb = (const float*)d_in[9];
    const float* ew1 = (const float*)d_in[10];
    const float* eb1 = (const float*)d_in[11];
    const float* ew2 = (const float*)d_in[12];
    const float* eb2 = (const float*)d_in[13];
    const float* elg = (const float*)d_in[14];
    const float* elb = (const float*)d_in[15];

    const int N = in_sizes[0] / 128;   // 50000
    const int E = in_sizes[2];         // 300000

    float* out_nodes = (float*)d_out;
    float* out_edges = out_nodes + (size_t)N * 128;

    // 1) fuse W1@W2 (+ bias), transpose, split to bf16 hi/lo
    prep_weights_kernel<<<642, 128>>>(nw1, nb1, nw2, nb2, ew1, eb1, ew2, eb2);

    // 2) agg = segment_sum(edge_features, receivers)
    zero_agg_kernel<<<(N * 32 + 255) / 256, 256>>>(N * 32);
    {
        long long threads = (long long)E * 32;
        int grid = (int)((threads + 255) / 256);
        scatter_add_kernel<<<grid, 256>>>(edge_f, receivers, E);
    }

    // 3) node pass: LN([node_f, agg] @ Wn + bn) -> out_nodes
    mlp_ln_kernel<0, 4><<<(N + 127) / 128, 256>>>(
        node_f, nullptr, nullptr, nlg, nlb, out_nodes, N);

    // 4) P pass: P = new_nodes @ [We_s|We_r] -> g_P (50k x 256)
    {
        dim3 grid((N + 127) / 128, 2);
        mlp_ln_kernel<1, 2><<<grid, 256>>>(
            out_nodes, nullptr, nullptr, nullptr, nullptr, nullptr, N);
    }

    // 5) edge pass: LN(ef @ We_e + P[s,0:128] + P[r,128:256] + be) -> out_edges
    mlp_ln_kernel<2, 2><<<(E + 127) / 128, 256>>>(
        edge_f, senders, receivers, elg, elb, out_edges, E);
}

// round 5
// speedup vs baseline: 1.5363x; 1.2477x over previous
#include <cuda_runtime.h>
#include <cuda_bf16.h>
#include <cstdint>

// ---------------------------------------------------------------------------
// GraphNetBlock, GB300 round 3.
//   agg = segment_sum(edge_features, receivers)             (red.v4 atomics)
//   new_nodes = LN( [node_f, agg] @ Wn + bn )
//   P         = new_nodes @ [We_s | We_r]        (50k x 256, per-NODE)
//   new_edges = LN( ef @ We_e + P[s,0:128] + P[r,128:256] + be )
// GEMMs: mma.sync m16n8k16 bf16, 3-term hi/lo split, ldmatrix B fragments.
// R3: __launch_bounds__(256,2) for 2 CTA/SM, A-prefetch, __ldcs for edge A.
// ---------------------------------------------------------------------------

#define NMAX 50000

static __device__ float g_agg[(size_t)NMAX * 128];
static __device__ float g_P[(size_t)NMAX * 256];
static __device__ __nv_bfloat16 g_nwT_hi[128 * 256];   // node fused W^T, pitch 256
static __device__ __nv_bfloat16 g_nwT_lo[128 * 256];
static __device__ __nv_bfloat16 g_PwT_hi[256 * 128];   // [We_s|We_r]^T, pitch 128
static __device__ __nv_bfloat16 g_PwT_lo[256 * 128];
static __device__ __nv_bfloat16 g_CwT_hi[128 * 128];   // We_e^T, pitch 128
static __device__ __nv_bfloat16 g_CwT_lo[128 * 128];
static __device__ float g_nbias[128];
static __device__ float g_ebias[128];

// --------------------------- weight prep -----------------------------------
__global__ void prep_weights_kernel(
    const float* __restrict__ nw1, const float* __restrict__ nb1,
    const float* __restrict__ nw2, const float* __restrict__ nb2,
    const float* __restrict__ ew1, const float* __restrict__ eb1,
    const float* __restrict__ ew2, const float* __restrict__ eb2)
{
    const int b = blockIdx.x;
    const int n = threadIdx.x;  // output column 0..127
    const float* row; const float* w2;
    __nv_bfloat16* dh = nullptr; __nv_bfloat16* dl = nullptr;
    float* bd = nullptr;
    float extra = 0.0f;
    int pitch = 0, kk = 0, row_off = 0;
    if (b < 256) {
        row = nw1 + (size_t)b * 128; w2 = nw2;
        dh = g_nwT_hi; dl = g_nwT_lo; pitch = 256; kk = b;
    } else if (b == 256) {
        row = nb1; w2 = nw2; bd = g_nbias; extra = nb2[n];
    } else if (b < 641) {
        int k = b - 257;           // 0..383 into edge W
        row = ew1 + (size_t)k * 128; w2 = ew2;
        if (k < 128)      { dh = g_PwT_hi; dl = g_PwT_lo; pitch = 128; row_off = 0;   kk = k; }
        else if (k < 256) { dh = g_PwT_hi; dl = g_PwT_lo; pitch = 128; row_off = 128; kk = k - 128; }
        else              { dh = g_CwT_hi; dl = g_CwT_lo; pitch = 128; row_off = 0;   kk = k - 256; }
    } else {
        row = eb1; w2 = ew2; bd = g_ebias; extra = eb2[n];
    }
    float s = extra;
    #pragma unroll 4
    for (int j = 0; j < 128; j++)
        s = fmaf(row[j], w2[j * 128 + n], s);
    if (bd) {
        bd[n] = s;
    } else {
        __nv_bfloat16 h = __float2bfloat16(s);
        float r = s - __bfloat162float(h);
        dh[(size_t)(row_off + n) * pitch + kk] = h;
        dl[(size_t)(row_off + n) * pitch + kk] = __float2bfloat16(r);
    }
}

// --------------------------- agg zero + scatter ----------------------------
__global__ void zero_agg_kernel(int n4)
{
    int i = blockIdx.x * blockDim.x + threadIdx.x;
    if (i < n4)
        reinterpret_cast<float4*>(g_agg)[i] = make_float4(0.f, 0.f, 0.f, 0.f);
}

// One warp per edge; lane c handles float4 chunk c (vector reduction to L2).
__global__ void scatter_add_kernel(const float* __restrict__ ef,
                                   const int* __restrict__ recv, int E)
{
    long long t = (long long)blockIdx.x * blockDim.x + threadIdx.x;
    int e = (int)(t >> 5);
    if (e >= E) return;
    int c = (int)(t & 31);
    float4 v = __ldcs(reinterpret_cast<const float4*>(ef) + (size_t)e * 32 + c);
    float* dst = g_agg + (size_t)recv[e] * 128 + c * 4;
    asm volatile("red.global.add.v4.f32 [%0], {%1,%2,%3,%4};"
                 :: "l"(dst), "f"(v.x), "f"(v.y), "f"(v.z), "f"(v.w)
                 : "memory");
}

// --------------------------- mma helpers -----------------------------------
__device__ __forceinline__ void mma16816(float c[4], const uint32_t a[4],
                                         uint32_t b0, uint32_t b1)
{
    asm volatile(
        "mma.sync.aligned.m16n8k16.row.col.f32.bf16.bf16.f32 "
        "{%0,%1,%2,%3}, {%4,%5,%6,%7}, {%8,%9}, {%0,%1,%2,%3};"
        : "+f"(c[0]), "+f"(c[1]), "+f"(c[2]), "+f"(c[3])
        : "r"(a[0]), "r"(a[1]), "r"(a[2]), "r"(a[3]), "r"(b0), "r"(b1));
}

__device__ __forceinline__ void ldsm4(uint32_t& r0, uint32_t& r1,
                                      uint32_t& r2, uint32_t& r3,
                                      const __nv_bfloat16* p)
{
    uint32_t a = (uint32_t)__cvta_generic_to_shared(p);
    asm volatile("ldmatrix.sync.aligned.m8n8.x4.shared.b16 {%0,%1,%2,%3}, [%4];"
                 : "=r"(r0), "=r"(r1), "=r"(r2), "=r"(r3) : "r"(a));
}

__device__ __forceinline__ void split_f2(float2 v, uint32_t& hi, uint32_t& lo)
{
    __nv_bfloat162 h = __float22bfloat162_rn(v);
    float2 hf = __bfloat1622float2(h);
    float2 r;
    r.x = v.x - hf.x;
    r.y = v.y - hf.y;
    __nv_bfloat162 l = __float22bfloat162_rn(r);
    hi = *reinterpret_cast<uint32_t*>(&h);
    lo = *reinterpret_cast<uint32_t*>(&l);
}

// --------------------------- fused GEMM kernels ----------------------------
// MODE 0: node pass.  A = [node_f | g_agg], K=256, epi: +nbias, LN -> out.
// MODE 1: P pass.     A = new_nodes, K=128, W col-block = blockIdx.y,
//                     epi: plain store into g_P (pitch 256).
// MODE 2: edge pass.  A = edge_f (streaming), K=128,
//                     epi: + g_P[s,0:128] + g_P[r,128:256] + ebias, LN -> out.
// CTA = 256 threads (8 warps), tile 128 rows x 128 cols; warp w rows w*16..+15.
template<int MODE, int NCHUNK>
__global__ __launch_bounds__(256, 2) void mlp_ln_kernel(
    const float* __restrict__ xA,
    const int* __restrict__ senders,
    const int* __restrict__ receivers,
    const float* __restrict__ ln_g,
    const float* __restrict__ ln_b,
    float* __restrict__ out, int M)
{
    __shared__ __nv_bfloat16 SBh[128 * 72];
    __shared__ __nv_bfloat16 SBl[128 * 72];
    __shared__ float s_bias[128], s_g[128], s_b[128];

    const int tid = threadIdx.x;
    const int warp = tid >> 5, lane = tid & 31;
    const int g = lane >> 2, q = lane & 3;
    const int laneRow = ((lane >> 4) << 3) + (lane & 7);
    const int laneK = ((lane >> 3) & 1) << 3;

    if (MODE != 1 && tid < 128) {
        s_bias[tid] = MODE ? g_ebias[tid] : g_nbias[tid];
        s_g[tid] = ln_g[tid];
        s_b[tid] = ln_b[tid];
    }

    const int row0 = blockIdx.x * 128 + warp * 16 + g;
    const int row1 = row0 + 8;
    const int r0c = min(row0, M - 1);
    const int r1c = min(row1, M - 1);

    const float* pA0 = xA + (size_t)r0c * 128;
    const float* pA1 = xA + (size_t)r1c * 128;
    const float* pG0 = g_agg + (size_t)r0c * 128;   // MODE 0 only
    const float* pG1 = g_agg + (size_t)r1c * 128;

    const __nv_bfloat16* Whi;
    const __nv_bfloat16* Wlo;
    int wpitch;
    int ncol0 = 0;
    if (MODE == 0) { Whi = g_nwT_hi; Wlo = g_nwT_lo; wpitch = 256; }
    else if (MODE == 1) {
        ncol0 = blockIdx.y * 128;
        Whi = g_PwT_hi + (size_t)ncol0 * 128;
        Wlo = g_PwT_lo + (size_t)ncol0 * 128;
        wpitch = 128;
    } else { Whi = g_CwT_hi; Wlo = g_CwT_lo; wpitch = 128; }

    float acc[16][4];
    #pragma unroll
    for (int i = 0; i < 16; i++) {
        acc[i][0] = 0.f; acc[i][1] = 0.f; acc[i][2] = 0.f; acc[i][3] = 0.f;
    }

    #pragma unroll
    for (int kc = 0; kc < NCHUNK; kc++) {
        __syncthreads();
        #pragma unroll
        for (int i = 0; i < 4; i++) {
            int idx = tid + i * 256;         // 0..1023
            int n = idx >> 3, j = idx & 7;   // smem row, int4-within-row
            reinterpret_cast<int4*>(SBh + n * 72)[j] =
                reinterpret_cast<const int4*>(Whi + (size_t)n * wpitch + kc * 64)[j];
            reinterpret_cast<int4*>(SBl + n * 72)[j] =
                reinterpret_cast<const int4*>(Wlo + (size_t)n * wpitch + kc * 64)[j];
        }
        __syncthreads();

        const float* pa;
        const float* pb;
        int cbase;
        if (MODE == 0) {
            pa = (kc < 2) ? pA0 : pG0;
            pb = (kc < 2) ? pA1 : pG1;
            cbase = (kc & 1) * 64;
        } else {
            pa = pA0; pb = pA1; cbase = kc * 64;
        }

        // prefetch A for ks=0
        float2 x00, x10, x01, x11;
        {
            const int c0 = q * 2;
            if (MODE == 2) {
                x00 = __ldcs(reinterpret_cast<const float2*>(pa + cbase + c0));
                x10 = __ldcs(reinterpret_cast<const float2*>(pb + cbase + c0));
                x01 = __ldcs(reinterpret_cast<const float2*>(pa + cbase + c0 + 8));
                x11 = __ldcs(reinterpret_cast<const float2*>(pb + cbase + c0 + 8));
            } else {
                x00 = *reinterpret_cast<const float2*>(pa + cbase + c0);
                x10 = *reinterpret_cast<const float2*>(pb + cbase + c0);
                x01 = *reinterpret_cast<const float2*>(pa + cbase + c0 + 8);
                x11 = *reinterpret_cast<const float2*>(pb + cbase + c0 + 8);
            }
        }

        #pragma unroll 1
        for (int ks = 0; ks < 4; ks++) {
            uint32_t ah[4], al[4];
            split_f2(x00, ah[0], al[0]);
            split_f2(x10, ah[1], al[1]);
            split_f2(x01, ah[2], al[2]);
            split_f2(x11, ah[3], al[3]);

            // prefetch A for ks+1 (overlaps the mma chain below)
            if (ks < 3) {
                const int c1 = (ks + 1) * 16 + q * 2;
                if (MODE == 2) {
                    x00 = __ldcs(reinterpret_cast<const float2*>(pa + cbase + c1));
                    x10 = __ldcs(reinterpret_cast<const float2*>(pb + cbase + c1));
                    x01 = __ldcs(reinterpret_cast<const float2*>(pa + cbase + c1 + 8));
                    x11 = __ldcs(reinterpret_cast<const float2*>(pb + cbase + c1 + 8));
                } else {
                    x00 = *reinterpret_cast<const float2*>(pa + cbase + c1);
                    x10 = *reinterpret_cast<const float2*>(pb + cbase + c1);
                    x01 = *reinterpret_cast<const float2*>(pa + cbase + c1 + 8);
                    x11 = *reinterpret_cast<const float2*>(pb + cbase + c1 + 8);
                }
            }

            const int kcol = ks * 16 + laneK;
            #pragma unroll
            for (int nt2 = 0; nt2 < 8; nt2++) {
                const int srow = nt2 * 16 + laneRow;
                uint32_t h0, h1, h2, h3, l0, l1, l2, l3;
                ldsm4(h0, h1, h2, h3, SBh + srow * 72 + kcol);
                ldsm4(l0, l1, l2, l3, SBl + srow * 72 + kcol);
                mma16816(acc[2 * nt2],     ah, h0, h1);
                mma16816(acc[2 * nt2 + 1], ah, h2, h3);
                mma16816(acc[2 * nt2],     al, h0, h1);
                mma16816(acc[2 * nt2 + 1], al, h2, h3);
                mma16816(acc[2 * nt2],     ah, l0, l1);
                mma16816(acc[2 * nt2 + 1], ah, l2, l3);
            }
        }
    }

    // ---------------- epilogues -------------------------------------------
    if (MODE == 1) {
        if (row0 < M) {
            float* o = g_P + (size_t)row0 * 256 + ncol0;
            #pragma unroll
            for (int nt = 0; nt < 16; nt++) {
                const int c = nt * 8 + q * 2;
                *reinterpret_cast<float2*>(o + c) = make_float2(acc[nt][0], acc[nt][1]);
            }
        }
        if (row1 < M) {
            float* o = g_P + (size_t)row1 * 256 + ncol0;
            #pragma unroll
            for (int nt = 0; nt < 16; nt++) {
                const int c = nt * 8 + q * 2;
                *reinterpret_cast<float2*>(o + c) = make_float2(acc[nt][2], acc[nt][3]);
            }
        }
        return;
    }

    if (MODE == 2) {
        const int s0 = senders[r0c], s1 = senders[r1c];
        const int d0 = receivers[r0c], d1 = receivers[r1c];
        const float* Ps0 = g_P + (size_t)s0 * 256;
        const float* Ps1 = g_P + (size_t)s1 * 256;
        const float* Pd0 = g_P + (size_t)d0 * 256 + 128;
        const float* Pd1 = g_P + (size_t)d1 * 256 + 128;
        #pragma unroll
        for (int nt = 0; nt < 16; nt++) {
            const int c = nt * 8 + q * 2;
            float2 a0 = *reinterpret_cast<const float2*>(Ps0 + c);
            float2 b0 = *reinterpret_cast<const float2*>(Pd0 + c);
            float2 a1 = *reinterpret_cast<const float2*>(Ps1 + c);
            float2 b1 = *reinterpret_cast<const float2*>(Pd1 + c);
            acc[nt][0] += a0.x + b0.x;
            acc[nt][1] += a0.y + b0.y;
            acc[nt][2] += a1.x + b1.x;
            acc[nt][3] += a1.y + b1.y;
        }
    }

    // bias + layernorm + store (MODE 0 and 2)
    float sum0 = 0.f, sq0 = 0.f, sum1 = 0.f, sq1 = 0.f;
    #pragma unroll
    for (int nt = 0; nt < 16; nt++) {
        const int c = nt * 8 + q * 2;
        const float b0 = s_bias[c], b1 = s_bias[c + 1];
        float v0 = acc[nt][0] + b0, v1 = acc[nt][1] + b1;
        float v2 = acc[nt][2] + b0, v3 = acc[nt][3] + b1;
        acc[nt][0] = v0; acc[nt][1] = v1; acc[nt][2] = v2; acc[nt][3] = v3;
        sum0 += v0 + v1; sq0 += v0 * v0 + v1 * v1;
        sum1 += v2 + v3; sq1 += v2 * v2 + v3 * v3;
    }
    #pragma unroll
    for (int m = 1; m <= 2; m <<= 1) {
        sum0 += __shfl_xor_sync(0xffffffffu, sum0, m);
        sq0  += __shfl_xor_sync(0xffffffffu, sq0, m);
        sum1 += __shfl_xor_sync(0xffffffffu, sum1, m);
        sq1  += __shfl_xor_sync(0xffffffffu, sq1, m);
    }
    const float inv = 1.0f / 128.0f;
    const float mu0 = sum0 * inv, mu1 = sum1 * inv;
    const float rs0 = rsqrtf(fmaxf(sq0 * inv - mu0 * mu0, 0.f) + 1e-5f);
    const float rs1 = rsqrtf(fmaxf(sq1 * inv - mu1 * mu1, 0.f) + 1e-5f);

    if (row0 < M) {
        float* o = out + (size_t)row0 * 128;
        #pragma unroll
        for (int nt = 0; nt < 16; nt++) {
            const int c = nt * 8 + q * 2;
            float2 w;
            w.x = (acc[nt][0] - mu0) * rs0 * s_g[c] + s_b[c];
            w.y = (acc[nt][1] - mu0) * rs0 * s_g[c + 1] + s_b[c + 1];
            *reinterpret_cast<float2*>(o + c) = w;
        }
    }
    if (row1 < M) {
        float* o = out + (size_t)row1 * 128;
        #pragma unroll
        for (int nt = 0; nt < 16; nt++) {
            const int c = nt * 8 + q * 2;
            float2 w;
            w.x = (acc[nt][2] - mu1) * rs1 * s_g[c] + s_b[c];
            w.y = (acc[nt][3] - mu1) * rs1 * s_g[c + 1] + s_b[c + 1];
            *reinterpret_cast<float2*>(o + c) = w;
        }
    }
}

// ---------------------------------------------------------------------------
extern "C" void kernel_launch(void* const* d_in, const int* in_sizes, int n_in,
                              void* d_out, int out_size)
{
    const float* node_f   = (const float*)d_in[0];
    const float* edge_f   = (const float*)d_in[1];
    const int*   senders  = (const int*)d_in[2];
    const int*   receivers= (const int*)d_in[3];
    const float* nw1 = (const float*)d_in[4];
    const float* nb1 = (const float*)d_in[5];
    const float* nw2 = (const float*)d_in[6];
    const float* nb2 = (const float*)d_in[7];
    const float* nlg = (const float*)d_in[8];
    const float* nlb = (const float*)d_in[9];
    const float* ew1 = (const float*)d_in[10];
    const float* eb1 = (const float*)d_in[11];
    const float* ew2 = (const float*)d_in[12];
    const float* eb2 = (const float*)d_in[13];
    const float* elg = (const float*)d_in[14];
    const float* elb = (const float*)d_in[15];

    const int N = in_sizes[0] / 128;   // 50000
    const int E = in_sizes[2];         // 300000

    float* out_nodes = (float*)d_out;
    float* out_edges = out_nodes + (size_t)N * 128;

    // 1) fuse W1@W2 (+ bias), transpose, split to bf16 hi/lo
    prep_weights_kernel<<<642, 128>>>(nw1, nb1, nw2, nb2, ew1, eb1, ew2, eb2);

    // 2) agg = segment_sum(edge_features, receivers)
    zero_agg_kernel<<<(N * 32 + 255) / 256, 256>>>(N * 32);
    {
        long long threads = (long long)E * 32;
        int grid = (int)((threads + 255) / 256);
        scatter_add_kernel<<<grid, 256>>>(edge_f, receivers, E);
    }

    // 3) node pass: LN([node_f, agg] @ Wn + bn) -> out_nodes
    mlp_ln_kernel<0, 4><<<(N + 127) / 128, 256>>>(
        node_f, nullptr, nullptr, nlg, nlb, out_nodes, N);

    // 4) P pass: P = new_nodes @ [We_s|We_r] -> g_P (50k x 256)
    {
        dim3 grid((N + 127) / 128, 2);
        mlp_ln_kernel<1, 2><<<grid, 256>>>(
            out_nodes, nullptr, nullptr, nullptr, nullptr, nullptr, N);
    }

    // 5) edge pass: LN(ef @ We_e + P[s,0:128] + P[r,128:256] + be) -> out_edges
    mlp_ln_kernel<2, 2><<<(E + 127) / 128, 256>>>(
        edge_f, senders, receivers, elg, elb, out_edges, E);
}